// round 1
// baseline (speedup 1.0000x reference)
#include <cuda_runtime.h>
#include <math.h>

#define NN 20480
#define EE 327680
#define GG 64
#define HD 256     // H*D
#define HH 4
#define DD 64
#define CC 10
#define NPG (NN/GG)   // 320 nodes per graph

// ---------------- scratch (static device globals; no allocation) ----------------
__device__ float g_z [NN*HD];
__device__ float g_hA[NN*HD];
__device__ float g_hB[NN*HD];
__device__ float g_el[NN*HH];
__device__ float g_er[NN*HH];
__device__ int   g_deg[NN];
__device__ int   g_rowptr[NN+1];
__device__ int   g_cursor[NN];
__device__ int   g_esrc[EE];

__device__ __forceinline__ float lrelu(float x) { return x > 0.f ? x : 0.2f * x; }
__device__ __forceinline__ float elu1 (float x) { return x > 0.f ? x : expm1f(x); }

// ---------------- CSR build ----------------
__global__ void zero_deg_kernel() {
    int i = blockIdx.x * blockDim.x + threadIdx.x;
    if (i < NN) g_deg[i] = 0;
}

__global__ void hist_kernel(const int* __restrict__ dst) {
    int i = blockIdx.x * blockDim.x + threadIdx.x;
    if (i < EE) atomicAdd(&g_deg[dst[i]], 1);
}

__global__ void scan_kernel() {   // one block, 512 threads, NN = 512*40
    __shared__ int part[512];
    const int CH = NN / 512;
    int t = threadIdx.x;
    int s = 0;
    for (int i = 0; i < CH; i++) s += g_deg[t*CH + i];
    part[t] = s;
    __syncthreads();
    if (t == 0) {
        int r = 0;
        for (int i = 0; i < 512; i++) { int v = part[i]; part[i] = r; r += v; }
        g_rowptr[NN] = r;
    }
    __syncthreads();
    int run = part[t];
    for (int i = 0; i < CH; i++) {
        int idx = t*CH + i;
        g_rowptr[idx] = run;
        g_cursor[idx] = run;
        run += g_deg[idx];
    }
}

__global__ void scatter_kernel(const int* __restrict__ src, const int* __restrict__ dst) {
    int i = blockIdx.x * blockDim.x + threadIdx.x;
    if (i < EE) {
        int p = atomicAdd(&g_cursor[dst[i]], 1);
        g_esrc[p] = src[i];
    }
}

// ---------------- GEMM: C[M,256] = A[M,K] @ B[K,256] ----------------
// 128x128 tile, 256 threads, 8x8 per thread, K-chunk 16.
__global__ __launch_bounds__(256) void gemm_kernel(const float* __restrict__ A,
                                                   const float* __restrict__ B,
                                                   float* __restrict__ C,
                                                   int K) {
    __shared__ float As[16][128];   // transposed: As[k][m]
    __shared__ float Bs[16][128];
    int tid = threadIdx.x;
    int bm = blockIdx.x * 128;
    int bn = blockIdx.y * 128;
    int tx = tid & 15, ty = tid >> 4;
    int row0 = ty * 8, col0 = tx * 8;

    float acc[8][8];
#pragma unroll
    for (int i = 0; i < 8; i++)
#pragma unroll
        for (int j = 0; j < 8; j++) acc[i][j] = 0.f;

    int a_row = tid >> 1;
    int a_col = (tid & 1) * 8;
    int b_row = tid >> 4;
    int b_col = (tid & 15) * 8;

    for (int k0 = 0; k0 < K; k0 += 16) {
        const float* ap = A + (size_t)(bm + a_row) * K + k0 + a_col;
        float4 av0 = *(const float4*)(ap);
        float4 av1 = *(const float4*)(ap + 4);
        const float* bp = B + (size_t)(k0 + b_row) * HD + bn + b_col;
        float4 bv0 = *(const float4*)(bp);
        float4 bv1 = *(const float4*)(bp + 4);

        As[a_col+0][a_row] = av0.x;  As[a_col+1][a_row] = av0.y;
        As[a_col+2][a_row] = av0.z;  As[a_col+3][a_row] = av0.w;
        As[a_col+4][a_row] = av1.x;  As[a_col+5][a_row] = av1.y;
        As[a_col+6][a_row] = av1.z;  As[a_col+7][a_row] = av1.w;
        *(float4*)&Bs[b_row][b_col]     = bv0;
        *(float4*)&Bs[b_row][b_col + 4] = bv1;
        __syncthreads();

#pragma unroll
        for (int k = 0; k < 16; k++) {
            float4 a0 = *(const float4*)&As[k][row0];
            float4 a1 = *(const float4*)&As[k][row0 + 4];
            float4 b0 = *(const float4*)&Bs[k][col0];
            float4 b1 = *(const float4*)&Bs[k][col0 + 4];
            float ar8[8] = {a0.x, a0.y, a0.z, a0.w, a1.x, a1.y, a1.z, a1.w};
            float br8[8] = {b0.x, b0.y, b0.z, b0.w, b1.x, b1.y, b1.z, b1.w};
#pragma unroll
            for (int i = 0; i < 8; i++)
#pragma unroll
                for (int j = 0; j < 8; j++)
                    acc[i][j] = fmaf(ar8[i], br8[j], acc[i][j]);
        }
        __syncthreads();
    }

#pragma unroll
    for (int i = 0; i < 8; i++) {
        float4 v0 = {acc[i][0], acc[i][1], acc[i][2], acc[i][3]};
        float4 v1 = {acc[i][4], acc[i][5], acc[i][6], acc[i][7]};
        float* cp = C + (size_t)(bm + row0 + i) * HD + bn + col0;
        *(float4*)(cp)     = v0;
        *(float4*)(cp + 4) = v1;
    }
}

// ---------------- attention projections: el/er [N,H] ----------------
__global__ void attn_kernel(const float* __restrict__ z,
                            const float* __restrict__ al,
                            const float* __restrict__ ar) {
    int gw   = (blockIdx.x * blockDim.x + threadIdx.x) >> 5;
    int lane = threadIdx.x & 31;
    if (gw >= NN) return;
    int hh = lane >> 3;
    int db = (lane & 7) * 8;

    const float4* zp = (const float4*)(z + (size_t)gw * HD + lane * 8);
    float4 z0 = zp[0], z1 = zp[1];
    const float4* ap = (const float4*)(al + hh * DD + db);
    float4 a0 = ap[0], a1 = ap[1];
    const float4* rp = (const float4*)(ar + hh * DD + db);
    float4 r0 = rp[0], r1 = rp[1];

    float dl = z0.x*a0.x + z0.y*a0.y + z0.z*a0.z + z0.w*a0.w
             + z1.x*a1.x + z1.y*a1.y + z1.z*a1.z + z1.w*a1.w;
    float dr = z0.x*r0.x + z0.y*r0.y + z0.z*r0.z + z0.w*r0.w
             + z1.x*r1.x + z1.y*r1.y + z1.z*r1.z + z1.w*r1.w;
#pragma unroll
    for (int o = 4; o >= 1; o >>= 1) {
        dl += __shfl_xor_sync(0xffffffffu, dl, o);
        dr += __shfl_xor_sync(0xffffffffu, dr, o);
    }
    if ((lane & 7) == 0) {
        g_el[gw * HH + hh] = dl;
        g_er[gw * HH + hh] = dr;
    }
}

// ---------------- per-node edge-softmax aggregation (warp per node) ----------------
__global__ __launch_bounds__(256) void agg_kernel(const float* __restrict__ z,
                                                  const float* __restrict__ hprev,
                                                  float* __restrict__ hout,
                                                  int residual) {
    int n    = (blockIdx.x * blockDim.x + threadIdx.x) >> 5;
    int lane = threadIdx.x & 31;
    if (n >= NN) return;

    int base = g_rowptr[n];
    int deg  = g_rowptr[n + 1] - base;
    float4 er4 = ((const float4*)g_er)[n];

    // pass A: per-head max of leaky(el[src]+er[n])
    float m0 = -1e30f, m1 = -1e30f, m2 = -1e30f, m3 = -1e30f;
    for (int k = lane; k < deg; k += 32) {
        int s = g_esrc[base + k];
        float4 e4 = ((const float4*)g_el)[s];
        m0 = fmaxf(m0, lrelu(e4.x + er4.x));
        m1 = fmaxf(m1, lrelu(e4.y + er4.y));
        m2 = fmaxf(m2, lrelu(e4.z + er4.z));
        m3 = fmaxf(m3, lrelu(e4.w + er4.w));
    }
#pragma unroll
    for (int o = 16; o >= 1; o >>= 1) {
        m0 = fmaxf(m0, __shfl_xor_sync(0xffffffffu, m0, o));
        m1 = fmaxf(m1, __shfl_xor_sync(0xffffffffu, m1, o));
        m2 = fmaxf(m2, __shfl_xor_sync(0xffffffffu, m2, o));
        m3 = fmaxf(m3, __shfl_xor_sync(0xffffffffu, m3, o));
    }

    int hh = lane >> 3;   // lane owns features lane*8..lane*8+7 -> head = lane/8

    float acc0 = 0.f, acc1 = 0.f, acc2 = 0.f, acc3 = 0.f;
    float acc4 = 0.f, acc5 = 0.f, acc6 = 0.f, acc7 = 0.f;
    float ssum = 0.f;

    for (int c = 0; c < deg; c += 32) {
        int rem = deg - c; if (rem > 32) rem = 32;
        int    s_l = 0;
        float4 w4  = {0.f, 0.f, 0.f, 0.f};
        if (lane < rem) {
            s_l = g_esrc[base + c + lane];
            float4 e4 = ((const float4*)g_el)[s_l];
            w4.x = __expf(lrelu(e4.x + er4.x) - m0);
            w4.y = __expf(lrelu(e4.y + er4.y) - m1);
            w4.z = __expf(lrelu(e4.z + er4.z) - m2);
            w4.w = __expf(lrelu(e4.w + er4.w) - m3);
        }
        for (int k = 0; k < rem; k++) {
            int   s  = __shfl_sync(0xffffffffu, s_l, k);
            float wx = __shfl_sync(0xffffffffu, w4.x, k);
            float wy = __shfl_sync(0xffffffffu, w4.y, k);
            float wz = __shfl_sync(0xffffffffu, w4.z, k);
            float ww = __shfl_sync(0xffffffffu, w4.w, k);
            float w  = (hh == 0) ? wx : (hh == 1) ? wy : (hh == 2) ? wz : ww;
            ssum += w;
            const float4* zr = (const float4*)(z + (size_t)s * HD + lane * 8);
            float4 a = zr[0], b = zr[1];
            acc0 = fmaf(w, a.x, acc0); acc1 = fmaf(w, a.y, acc1);
            acc2 = fmaf(w, a.z, acc2); acc3 = fmaf(w, a.w, acc3);
            acc4 = fmaf(w, b.x, acc4); acc5 = fmaf(w, b.y, acc5);
            acc6 = fmaf(w, b.z, acc6); acc7 = fmaf(w, b.w, acc7);
        }
    }

    float inv = 1.f / ssum;   // deg >= 1 guaranteed -> ssum > 0
    float o8[8] = {acc0*inv, acc1*inv, acc2*inv, acc3*inv,
                   acc4*inv, acc5*inv, acc6*inv, acc7*inv};
    size_t ob = (size_t)n * HD + lane * 8;
    if (residual) {
        const float4* pp = (const float4*)(hprev + ob);
        float4 p0 = pp[0], p1 = pp[1];
        float pr[8] = {p0.x, p0.y, p0.z, p0.w, p1.x, p1.y, p1.z, p1.w};
#pragma unroll
        for (int i = 0; i < 8; i++) o8[i] = elu1(o8[i] + pr[i]);  // GATConv-internal ELU
    }
#pragma unroll
    for (int i = 0; i < 8; i++) o8[i] = elu1(o8[i]);              // model-level ELU
    float4 v0 = {o8[0], o8[1], o8[2], o8[3]};
    float4 v1 = {o8[4], o8[5], o8[6], o8[7]};
    *(float4*)(hout + ob)     = v0;
    *(float4*)(hout + ob + 4) = v1;
}

// ---------------- pooling + classifier ----------------
__global__ __launch_bounds__(256) void pool_kernel(const float* __restrict__ h,
                                                   const float* __restrict__ Wc,
                                                   const float* __restrict__ bc,
                                                   float* __restrict__ out) {
    __shared__ float hg[HD];
    int g = blockIdx.x;
    int t = threadIdx.x;
    float s = 0.f;
    const float* base = h + (size_t)g * NPG * HD + t;
    for (int i = 0; i < NPG; i++) s += base[(size_t)i * HD];
    hg[t] = elu1(s * (1.f / NPG));
    __syncthreads();
    if (t < CC) {
        float acc = bc[t];
        for (int f = 0; f < HD; f++) acc = fmaf(hg[f], Wc[f * CC + t], acc);
        out[g * CC + t] = acc;
    }
}

// ---------------- launch ----------------
extern "C" void kernel_launch(void* const* d_in, const int* in_sizes, int n_in,
                              void* d_out, int out_size) {
    const float* x   = (const float*)d_in[0];
    const int*   src = (const int*)  d_in[1];
    const int*   dst = (const int*)  d_in[2];
    const float* W0  = (const float*)d_in[4];
    const float* al0 = (const float*)d_in[5];
    const float* ar0 = (const float*)d_in[6];
    const float* W1  = (const float*)d_in[7];
    const float* al1 = (const float*)d_in[8];
    const float* ar1 = (const float*)d_in[9];
    const float* W2  = (const float*)d_in[10];
    const float* al2 = (const float*)d_in[11];
    const float* ar2 = (const float*)d_in[12];
    const float* Wc  = (const float*)d_in[13];
    const float* bc  = (const float*)d_in[14];
    float* out = (float*)d_out;

    float *z, *hA, *hB;
    cudaGetSymbolAddress((void**)&z,  g_z);
    cudaGetSymbolAddress((void**)&hA, g_hA);
    cudaGetSymbolAddress((void**)&hB, g_hB);

    // CSR by dst (deterministic work; intra-bucket order only perturbs fp sum order)
    zero_deg_kernel<<<(NN + 255) / 256, 256>>>();
    hist_kernel<<<(EE + 255) / 256, 256>>>(dst);
    scan_kernel<<<1, 512>>>();
    scatter_kernel<<<(EE + 255) / 256, 256>>>(src, dst);

    dim3 ggrid(NN / 128, HD / 128);

    // layer 0 (no residual)
    gemm_kernel<<<ggrid, 256>>>(x, W0, z, 128);
    attn_kernel<<<NN / 8, 256>>>(z, al0, ar0);
    agg_kernel<<<NN / 8, 256>>>(z, nullptr, hA, 0);

    // layer 1 (residual)
    gemm_kernel<<<ggrid, 256>>>(hA, W1, z, 256);
    attn_kernel<<<NN / 8, 256>>>(z, al1, ar1);
    agg_kernel<<<NN / 8, 256>>>(z, hA, hB, 1);

    // layer 2 (residual)
    gemm_kernel<<<ggrid, 256>>>(hB, W2, z, 256);
    attn_kernel<<<NN / 8, 256>>>(z, al2, ar2);
    agg_kernel<<<NN / 8, 256>>>(z, hB, hA, 1);

    pool_kernel<<<GG, 256>>>(hA, Wc, bc, out);
}